// round 5
// baseline (speedup 1.0000x reference)
#include <cuda_runtime.h>
#include <cstdint>

// Problem dims (fixed by the reference: B=4, S=2048, H=2048, I=8192)
#define M_TOK 8192      // B*S tokens
#define H_DIM 2048
#define I_DIM 8192
#define N1    16384     // 2*I  (GeGLU: [gelu-branch | linear-branch])
#define LN_EPS 1e-6f

// ---------------------------------------------------------------------------
// Scratch (device globals; allocation-free per harness rules)
// ---------------------------------------------------------------------------
__device__ float g_Y [(size_t)M_TOK * H_DIM];   //  67 MB  LN output (tf32-rounded)
__device__ float g_W1[(size_t)H_DIM * N1];      // 134 MB  kernel_1 tf32-rounded
__device__ float g_W2[(size_t)I_DIM * H_DIM];   //  67 MB  kernel_2 tf32-rounded
__device__ float g_H [(size_t)M_TOK * N1];      // 536 MB  GEMM1 output (fp32)
__device__ float g_Z [(size_t)M_TOK * I_DIM];   // 268 MB  GeGLU output (tf32-rounded)

// ---------------------------------------------------------------------------
// Helpers
// ---------------------------------------------------------------------------
__device__ __forceinline__ float to_tf32(float x) {
    // Round-to-nearest tf32 (RNA). Feeding raw fp32 to the MMA truncates and
    // introduces a correlated low bias over the K-reduction -> rel_err blowup.
    uint32_t u;
    asm("cvt.rna.tf32.f32 %0, %1;" : "=r"(u) : "f"(x));
    return __uint_as_float(u);
}

__device__ __forceinline__ void cp_async16(void* smem, const void* gmem) {
    unsigned s = (unsigned)__cvta_generic_to_shared(smem);
    asm volatile("cp.async.cg.shared.global [%0], [%1], 16;\n" :: "r"(s), "l"(gmem) : "memory");
}
__device__ __forceinline__ void cp_commit() {
    asm volatile("cp.async.commit_group;\n" ::: "memory");
}
__device__ __forceinline__ void cp_wait1() {
    asm volatile("cp.async.wait_group 1;\n" ::: "memory");
}

__device__ __forceinline__ void mma_tf32(float c[4], const uint32_t a[4], const uint32_t b[2]) {
    asm volatile(
        "mma.sync.aligned.m16n8k8.row.col.f32.tf32.tf32.f32 "
        "{%0,%1,%2,%3}, {%4,%5,%6,%7}, {%8,%9}, {%0,%1,%2,%3};\n"
        : "+f"(c[0]), "+f"(c[1]), "+f"(c[2]), "+f"(c[3])
        : "r"(a[0]), "r"(a[1]), "r"(a[2]), "r"(a[3]), "r"(b[0]), "r"(b[1]));
}

__device__ __forceinline__ float gelu_tanh(float v) {
    // flax approximate gelu: 0.5*x*(1+tanh(sqrt(2/pi)*(x+0.044715 x^3)))
    float u = 0.7978845608028654f * (v + 0.044715f * v * v * v);
    return 0.5f * v * (1.0f + tanhf(u));
}

// ---------------------------------------------------------------------------
// 1) LayerNorm: one CTA per token row (H=2048 held in registers, two reductions)
// ---------------------------------------------------------------------------
__global__ void __launch_bounds__(256)
ln_kernel(const float* __restrict__ x, const float* __restrict__ gamma,
          const float* __restrict__ beta, float* __restrict__ y)
{
    __shared__ float red1[8], red2[8];
    const int row  = blockIdx.x;
    const int t    = threadIdx.x;
    const int lane = t & 31, w = t >> 5;

    const float4* xr = (const float4*)(x + (size_t)row * H_DIM);
    float4 v0 = xr[t];
    float4 v1 = xr[t + 256];

    float s = v0.x + v0.y + v0.z + v0.w + v1.x + v1.y + v1.z + v1.w;
    #pragma unroll
    for (int o = 16; o > 0; o >>= 1) s += __shfl_xor_sync(0xffffffffu, s, o);
    if (lane == 0) red1[w] = s;
    __syncthreads();
    float tot = 0.f;
    #pragma unroll
    for (int i = 0; i < 8; i++) tot += red1[i];
    const float mu = tot * (1.0f / H_DIM);

    float d[8] = {v0.x - mu, v0.y - mu, v0.z - mu, v0.w - mu,
                  v1.x - mu, v1.y - mu, v1.z - mu, v1.w - mu};
    float ss = 0.f;
    #pragma unroll
    for (int i = 0; i < 8; i++) ss += d[i] * d[i];
    #pragma unroll
    for (int o = 16; o > 0; o >>= 1) ss += __shfl_xor_sync(0xffffffffu, ss, o);
    if (lane == 0) red2[w] = ss;
    __syncthreads();
    float tot2 = 0.f;
    #pragma unroll
    for (int i = 0; i < 8; i++) tot2 += red2[i];
    const float rstd = rsqrtf(tot2 * (1.0f / H_DIM) + LN_EPS);

    const float4* g4 = (const float4*)gamma;
    const float4* b4 = (const float4*)beta;
    float4 ga = g4[t], gb = g4[t + 256];
    float4 ba = b4[t], bb = b4[t + 256];

    float4 o0, o1;
    o0.x = to_tf32(d[0] * rstd * ga.x + ba.x);
    o0.y = to_tf32(d[1] * rstd * ga.y + ba.y);
    o0.z = to_tf32(d[2] * rstd * ga.z + ba.z);
    o0.w = to_tf32(d[3] * rstd * ga.w + ba.w);
    o1.x = to_tf32(d[4] * rstd * gb.x + bb.x);
    o1.y = to_tf32(d[5] * rstd * gb.y + bb.y);
    o1.z = to_tf32(d[6] * rstd * gb.z + bb.z);
    o1.w = to_tf32(d[7] * rstd * gb.w + bb.w);

    float4* yr = (float4*)(y + (size_t)row * H_DIM);
    yr[t]       = o0;
    yr[t + 256] = o1;
}

// ---------------------------------------------------------------------------
// 2) Weight tf32-round (elementwise)
// ---------------------------------------------------------------------------
__global__ void __launch_bounds__(256)
cvt_kernel(const float4* __restrict__ in, float4* __restrict__ out, int n4)
{
    int i = blockIdx.x * 256 + threadIdx.x;
    if (i < n4) {
        float4 v = in[i];
        v.x = to_tf32(v.x); v.y = to_tf32(v.y);
        v.z = to_tf32(v.z); v.w = to_tf32(v.w);
        out[i] = v;
    }
}

// ---------------------------------------------------------------------------
// 3) TF32 GEMM: C[M,N] = A[M,K] (row-major) * B[K,N] (row-major), fp32 accum.
//    CTA tile 128x128x32, 8 warps (4m x 2n), warp tile 32x64, double-buffered
//    cp.async. All dims are multiples of the tiles (no predication).
// ---------------------------------------------------------------------------
#define BM 128
#define BN 128
#define BK 32
#define ASTR 36      // pad: bank = (4*row + col) % 32 -> conflict-free frag loads
#define BSTR 136     // pad: bank = (8*k + n) % 32   -> conflict-free frag loads
#define AS_BUF (BM * ASTR)               // 4608 floats
#define BS_BUF (BK * BSTR)               // 4352 floats
#define GEMM_SMEM_BYTES ((2 * AS_BUF + 2 * BS_BUF) * 4)   // 71680 B

__global__ void __launch_bounds__(256)
gemm_tf32(const float* __restrict__ A, const float* __restrict__ Bm,
          float* __restrict__ C, int M, int N, int K)
{
    extern __shared__ float sm[];
    float* As = sm;
    float* Bs = sm + 2 * AS_BUF;

    const int tid  = threadIdx.x;
    const int lane = tid & 31;
    const int wid  = tid >> 5;
    const int wm   = wid & 3;   // 0..3 -> 32-row slab
    const int wn   = wid >> 2;  // 0..1 -> 64-col slab
    const int m0   = blockIdx.y * BM;
    const int n0   = blockIdx.x * BN;

    float acc[2][8][4];
    #pragma unroll
    for (int i = 0; i < 2; i++)
        #pragma unroll
        for (int j = 0; j < 8; j++)
            #pragma unroll
            for (int q = 0; q < 4; q++) acc[i][j][q] = 0.f;

    const int NK = K / BK;

    auto load_tiles = [&](int buf, int kt) {
        const float* Ag = A  + (size_t)m0 * K + kt * BK;
        const float* Bg = Bm + (size_t)(kt * BK) * N + n0;
        float* as = As + buf * AS_BUF;
        float* bs = Bs + buf * BS_BUF;
        #pragma unroll
        for (int i = 0; i < 4; i++) {                 // A: 128 rows x 32 cols
            int idx = tid + i * 256;
            int r = idx >> 3, c = (idx & 7) << 2;
            cp_async16(as + r * ASTR + c, Ag + (size_t)r * K + c);
        }
        #pragma unroll
        for (int i = 0; i < 4; i++) {                 // B: 32 rows x 128 cols
            int idx = tid + i * 256;
            int k = idx >> 5, c = (idx & 31) << 2;
            cp_async16(bs + k * BSTR + c, Bg + (size_t)k * N + c);
        }
    };

    load_tiles(0, 0);
    cp_commit();

    for (int kt = 0; kt < NK; ++kt) {
        if (kt + 1 < NK) load_tiles((kt + 1) & 1, kt + 1);
        cp_commit();
        cp_wait1();
        __syncthreads();

        const float* as = As + (kt & 1) * AS_BUF;
        const float* bs = Bs + (kt & 1) * BS_BUF;

        #pragma unroll
        for (int ks = 0; ks < BK / 8; ++ks) {
            uint32_t af[2][4], bf[8][2];
            const int ar = wm * 32 + (lane >> 2);
            const int ac = ks * 8 + (lane & 3);
            #pragma unroll
            for (int mt = 0; mt < 2; ++mt) {
                const float* ap = as + (ar + mt * 16) * ASTR + ac;
                af[mt][0] = __float_as_uint(ap[0]);
                af[mt][1] = __float_as_uint(ap[8 * ASTR]);
                af[mt][2] = __float_as_uint(ap[4]);
                af[mt][3] = __float_as_uint(ap[8 * ASTR + 4]);
            }
            const int bk = ks * 8 + (lane & 3);
            const int bn = wn * 64 + (lane >> 2);
            #pragma unroll
            for (int nt = 0; nt < 8; ++nt) {
                const float* bp = bs + bk * BSTR + bn + nt * 8;
                bf[nt][0] = __float_as_uint(bp[0]);
                bf[nt][1] = __float_as_uint(bp[4 * BSTR]);
            }
            #pragma unroll
            for (int mt = 0; mt < 2; ++mt)
                #pragma unroll
                for (int nt = 0; nt < 8; ++nt)
                    mma_tf32(acc[mt][nt], af[mt], bf[nt]);
        }
        __syncthreads();
    }

    // Epilogue: fp32 stores (float2, 8B aligned)
    #pragma unroll
    for (int mt = 0; mt < 2; ++mt) {
        const int r = m0 + wm * 32 + mt * 16 + (lane >> 2);
        #pragma unroll
        for (int nt = 0; nt < 8; ++nt) {
            const int c = n0 + wn * 64 + nt * 8 + 2 * (lane & 3);
            *(float2*)(C + (size_t)r * N + c)       = make_float2(acc[mt][nt][0], acc[mt][nt][1]);
            *(float2*)(C + (size_t)(r + 8) * N + c) = make_float2(acc[mt][nt][2], acc[mt][nt][3]);
        }
    }
}

// ---------------------------------------------------------------------------
// 4) GeGLU: z = gelu(h[:, 0:I]) * h[:, I:2I], tf32-rounded for GEMM2
// ---------------------------------------------------------------------------
__global__ void __launch_bounds__(256)
geglu_kernel(const float* __restrict__ h, float* __restrict__ z)
{
    const int idx = blockIdx.x * 256 + threadIdx.x;   // over M_TOK*I/4
    const int row = idx >> 11;                        // I/4 = 2048 float4 per row
    const int c4  = idx & 2047;

    const float4 a = *((const float4*)(h + (size_t)row * N1) + c4);
    const float4 b = *((const float4*)(h + (size_t)row * N1 + I_DIM) + c4);
    float4 o;
    o.x = to_tf32(gelu_tanh(a.x) * b.x);
    o.y = to_tf32(gelu_tanh(a.y) * b.y);
    o.z = to_tf32(gelu_tanh(a.z) * b.z);
    o.w = to_tf32(gelu_tanh(a.w) * b.w);
    *((float4*)(z + (size_t)row * I_DIM) + c4) = o;
}

// ---------------------------------------------------------------------------
// Launch
// ---------------------------------------------------------------------------
extern "C" void kernel_launch(void* const* d_in, const int* in_sizes, int n_in,
                              void* d_out, int out_size)
{
    (void)in_sizes; (void)n_in; (void)out_size;
    const float* x     = (const float*)d_in[0];
    const float* gamma = (const float*)d_in[1];
    const float* beta  = (const float*)d_in[2];
    const float* k1    = (const float*)d_in[3];
    const float* k2    = (const float*)d_in[4];
    float* out = (float*)d_out;

    float *Y, *W1, *W2, *Hb, *Z;
    cudaGetSymbolAddress((void**)&Y,  g_Y);
    cudaGetSymbolAddress((void**)&W1, g_W1);
    cudaGetSymbolAddress((void**)&W2, g_W2);
    cudaGetSymbolAddress((void**)&Hb, g_H);
    cudaGetSymbolAddress((void**)&Z,  g_Z);

    cudaFuncSetAttribute(gemm_tf32, cudaFuncAttributeMaxDynamicSharedMemorySize,
                         GEMM_SMEM_BYTES);

    // 1) LayerNorm -> Y (tf32-rounded)
    ln_kernel<<<M_TOK, 256>>>(x, gamma, beta, Y);

    // 2) Weights -> tf32-rounded copies
    cvt_kernel<<<(H_DIM * N1 / 4) / 256, 256>>>((const float4*)k1, (float4*)W1, H_DIM * N1 / 4);
    cvt_kernel<<<(I_DIM * H_DIM / 4) / 256, 256>>>((const float4*)k2, (float4*)W2, I_DIM * H_DIM / 4);

    // 3) GEMM1: H = Y[8192,2048] @ W1[2048,16384]
    gemm_tf32<<<dim3(N1 / BN, M_TOK / BM), 256, GEMM_SMEM_BYTES>>>(Y, W1, Hb, M_TOK, N1, H_DIM);

    // 4) GeGLU -> Z (tf32-rounded)
    geglu_kernel<<<(M_TOK * I_DIM / 4) / 256, 256>>>(Hb, Z);

    // 5) GEMM2: out = Z[8192,8192] @ W2[8192,2048]
    gemm_tf32<<<dim3(H_DIM / BN, M_TOK / BM), 256, GEMM_SMEM_BYTES>>>(Z, W2, out, M_TOK, H_DIM, I_DIM);
}